// round 12
// baseline (speedup 1.0000x reference)
#include <cuda_runtime.h>

#define NW 10
typedef unsigned long long u64;

// Precomputed param-only phase tables, natural s order: [pass = k*2+ry][s]
__device__ float2 g_tab[8][1024];

// ---------- packed f32x2 helpers (lo = batch elem 0, hi = elem 1) ----------
__device__ __forceinline__ u64 pk2(float x, float y) {
    u64 r; asm("mov.b64 %0, {%1,%2};" : "=l"(r) : "f"(x), "f"(y)); return r;
}
__device__ __forceinline__ void upk2(u64 v, float &x, float &y) {
    asm("mov.b64 {%0,%1}, %2;" : "=f"(x), "=f"(y) : "l"(v));
}
__device__ __forceinline__ u64 pfma(u64 a, u64 b, u64 c) {
    u64 d; asm("fma.rn.f32x2 %0, %1, %2, %3;" : "=l"(d) : "l"(a), "l"(b), "l"(c)); return d;
}
__device__ __forceinline__ u64 pmul(u64 a, u64 b) {
    u64 d; asm("mul.rn.f32x2 %0, %1, %2;" : "=l"(d) : "l"(a), "l"(b)); return d;
}
__device__ __forceinline__ u64 padd(u64 a, u64 b) {
    u64 d; asm("add.rn.f32x2 %0, %1, %2;" : "=l"(d) : "l"(a), "l"(b)); return d;
}
__device__ __forceinline__ u64 dup2(float v) { return pk2(v, v); }

// ---------- ring-CNOT permutation: GF(2)-linear basis images (bit 0 = LSB) ----------
__host__ __device__ constexpr int PBf(int p) {
    return p==0?769 : p==1?3 : p==2?6 : p==3?12 : p==4?24
         : p==5?48 : p==6?96 : p==7?192 : p==8?384 : 768;
}
// perm image of j-part (j bits 0..2 <-> state bits 7..9)
__host__ __device__ constexpr int permJ4(int j) {
    return ((j&1)?PBf(7):0) ^ ((j&2)?PBf(8):0) ^ ((j&4)?PBf(9):0);
}

// ---------- table precompute (params-only phases incl. perm-composed) ----------
__global__ void precompute_tables(const float* __restrict__ params) {
    int p = blockIdx.x;          // 0..7
    int s = threadIdx.x;         // 0..1023
    int k = p >> 1, ry = p & 1;

    int idx = s;
    for (int q = 9; q >= 0; --q) {
        int c = q, t = (q + 1) % NW;
        int bit = (idx >> (9 - c)) & 1;
        idx ^= bit << (9 - t);
    }

    const float* thA = params + (k * 6 + (ry ? 5 : 2)) * NW;
    float ang = 0.f;
#pragma unroll
    for (int w = 0; w < NW; w++)
        ang += thA[w] * ((float)((idx >> (9 - w)) & 1) - 0.5f);

    if (ry == 0) {
        const float* th3 = params + (k * 6 + 3) * NW;
#pragma unroll
        for (int w = 0; w < NW; w++)
            ang += th3[w] * ((float)((s >> (9 - w)) & 1) - 0.5f);
    } else if (k < 3) {
        const float* th0 = params + ((k + 1) * 6) * NW;
#pragma unroll
        for (int w = 0; w < NW; w++)
            ang += th0[w] * ((float)((s >> (9 - w)) & 1) - 0.5f);
    }
    float sn, cn;
    sincosf(ang, &sn, &cn);
    g_tab[p][s] = make_float2(cn, sn);
}

// ---------- main kernel: 4 warps per CTA, CTA handles a batch PAIR ----------
// state index s = (j<<7) | (wp<<5) | lane
//   wires 0..2 <-> j bits 2..0     (register butterflies)
//   wires 3,4  <-> wp bits 1,0     (fused into perm gather, 4-point)
//   wires 5..9 <-> lane bits 4..0  (shfl butterflies)
// Each u64 holds (elem0, elem1) of the same amplitude component.
__global__ __launch_bounds__(128, 6)
void quantum_pair_kernel(const float* __restrict__ x,
                         const float* __restrict__ params,
                         float* __restrict__ out)
{
    __shared__ u64    sbr[1024];    // re exchange
    __shared__ u64    sbi[1024];    // im exchange
    __shared__ float2 scs[80];      // RY (cos,sin) per [k*2+ry][wire]
    __shared__ u64    wredS[4][NW];

    const int tid  = threadIdx.x;
    const int lane = tid & 31;
    const int wp   = tid >> 5;
    const int b0   = 2 * blockIdx.x;
    const int sThread = (wp << 5) | lane;   // state bits 0..6

    // RY coefficient tables (half angles)
    for (int i = tid; i < 80; i += 128) {
        int k = i / 20, r = (i / 10) % 2, w = i % 10;
        float th = 0.5f * params[(k * 6 + (r ? 4 : 1)) * NW + w];
        scs[i] = make_float2(cosf(th), sinf(th));
    }

    // encoding: thread-constant part (wires 3..9) + packed half-values (wires 0..2)
    float xb0 = 0.f, xb1 = 0.f;
#pragma unroll
    for (int w = 3; w < NW; w++) {
        float bit = (float)((sThread >> (9 - w)) & 1) - 0.5f;
        xb0 += x[b0 * NW + w] * bit;
        xb1 += x[(b0 + 1) * NW + w] * bit;
    }
    const u64 xbaseP = pk2(xb0, xb1);
    u64 hP[3], nhP[3];
#pragma unroll
    for (int w = 0; w < 3; w++) {
        float a0 = 0.5f * x[b0 * NW + w], a1 = 0.5f * x[(b0 + 1) * NW + w];
        hP[w]  = pk2(a0, a1);
        nhP[w] = pk2(-a0, -a1);
    }

    // perm image of thread part (state bits 0..6)
    int B = 0;
#pragma unroll
    for (int p = 0; p < 5; p++) if ((lane >> p) & 1) B ^= PBf(p);
    if (wp & 1) B ^= PBf(5);
    if (wp & 2) B ^= PBf(6);
    const int B5 = (B >> 5) & 1;
    const int B6 = (B >> 6) & 1;

    // ---- init: |0>, block-0 rz(p0) folded in (same phase for both elems) ----
    u64 sre[8], sim[8];
#pragma unroll
    for (int j = 0; j < 8; j++) { sre[j] = 0ull; sim[j] = 0ull; }
    if (tid == 0) {
        float a = 0.f;
#pragma unroll
        for (int w = 0; w < NW; w++) a -= 0.5f * params[w];
        float sn, cn; sincosf(a, &sn, &cn);
        sre[0] = dup2(cn);
        sim[0] = dup2(sn);
    }
    __syncthreads();   // scs ready

    // ============================ circuit ============================
#pragma unroll 1
    for (int k = 0; k < 4; k++) {
#pragma unroll 1
        for (int ry = 0; ry < 2; ry++) {
            const float2* cs = scs + (k * 2 + ry) * NW;

            // ---- RY register wires 0..2 (j-bit butterflies) ----
#pragma unroll
            for (int w = 0; w < 3; w++) {
                float2 c = cs[w];
                u64 c2 = dup2(c.x), s2 = dup2(c.y), ns2 = dup2(-c.y);
                const int m = 1 << (2 - w);
#pragma unroll
                for (int j = 0; j < 8; j++) {
                    if (!(j & m)) {
                        u64 r0 = sre[j], r1 = sre[j | m];
                        sre[j]     = pfma(c2, r0, pmul(ns2, r1));
                        sre[j | m] = pfma(s2, r0, pmul(c2, r1));
                        u64 i0 = sim[j], i1 = sim[j | m];
                        sim[j]     = pfma(c2, i0, pmul(ns2, i1));
                        sim[j | m] = pfma(s2, i0, pmul(c2, i1));
                    }
                }
            }

            // ---- RY lane wires 5..9 (shfl butterflies) ----
#pragma unroll
            for (int w = 5; w < 10; w++) {
                float2 c = cs[w];
                u64 c2   = dup2(c.x);
                u64 coef = ((lane >> (9 - w)) & 1) ? dup2(c.y) : dup2(-c.y);
                const int m = 1 << (9 - w);
#pragma unroll
                for (int j = 0; j < 8; j++) {
                    u64 pr = __shfl_xor_sync(0xFFFFFFFFu, sre[j], m);
                    sre[j] = pfma(c2, sre[j], pmul(coef, pr));
                    u64 pi = __shfl_xor_sync(0xFFFFFFFFu, sim[j], m);
                    sim[j] = pfma(c2, sim[j], pmul(coef, pi));
                }
            }

            // ---- cross-warp wires 3 (bit6) & 4 (bit5): fused into perm gather ----
            // rows of rotation at source index t = perm(s):
            //   t5 = B5 (thread-const), t6 = B6 ^ (j&1) (compile-time select)
            float2 c3 = cs[3], c4 = cs[4];
            u64 r40  = B5 ? dup2(c4.y) : dup2(c4.x);
            u64 r41  = B5 ? dup2(c4.x) : dup2(-c4.y);
            u64 r30E = B6 ? dup2(c3.y) : dup2(c3.x);
            u64 r31E = B6 ? dup2(c3.x) : dup2(-c3.y);
            u64 r30O = B6 ? dup2(c3.x) : dup2(c3.y);
            u64 r31O = B6 ? dup2(-c3.y) : dup2(c3.x);

            __syncthreads();   // prior gather reads complete
#pragma unroll
            for (int j = 0; j < 8; j++) {
                sbr[(j << 7) | sThread] = sre[j];
                sbi[(j << 7) | sThread] = sim[j];
            }
            __syncthreads();

            const float2* __restrict__ tab = g_tab[k * 2 + ry];
            const bool doEnc = (ry == 1) && (k < 3);

#pragma unroll
            for (int j = 0; j < 8; j++) {
                const int base = (B ^ permJ4(j)) & ~0x60;
                const u64 r30 = (j & 1) ? r30O : r30E;
                const u64 r31 = (j & 1) ? r31O : r31E;

                u64 in0r = pfma(r40, sbr[base],        pmul(r41, sbr[base ^ 32]));
                u64 in1r = pfma(r40, sbr[base ^ 64],   pmul(r41, sbr[base ^ 96]));
                u64 vre  = pfma(r30, in0r, pmul(r31, in1r));
                u64 in0i = pfma(r40, sbi[base],        pmul(r41, sbi[base ^ 32]));
                u64 in1i = pfma(r40, sbi[base ^ 64],   pmul(r41, sbi[base ^ 96]));
                u64 vim  = pfma(r30, in0i, pmul(r31, in1i));

                // param diagonal (shared across pair)
                float2 tt = tab[(j << 7) | sThread];
                u64 cnP = dup2(tt.x), snP = dup2(tt.y), nsnP = dup2(-tt.y);
                u64 rr = pfma(cnP, vre, pmul(nsnP, vim));
                u64 ii = pfma(snP, vre, pmul(cnP, vim));

                if (doEnc) {
                    u64 aP = padd(xbaseP, (j & 4) ? hP[0] : nhP[0]);
                    aP = padd(aP, (j & 2) ? hP[1] : nhP[1]);
                    aP = padd(aP, (j & 1) ? hP[2] : nhP[2]);
                    float a0, a1; upk2(aP, a0, a1);
                    float s0, c0, s1, c1;
                    __sincosf(a0, &s0, &c0);
                    __sincosf(a1, &s1, &c1);
                    u64 ceP = pk2(c0, c1), seP = pk2(s0, s1), nseP = pk2(-s0, -s1);
                    sre[j] = pfma(ceP, rr, pmul(nseP, ii));
                    sim[j] = pfma(seP, rr, pmul(ceP, ii));
                } else {
                    sre[j] = rr;
                    sim[j] = ii;
                }
            }
        }
    }

    // ============================ measurement ============================
    const u64 negOne = pk2(-1.f, -1.f);
    u64 pt = 0ull, aj0 = 0ull, aj1 = 0ull, aj2 = 0ull;
#pragma unroll
    for (int j = 0; j < 8; j++) {
        u64 pr  = pfma(sre[j], sre[j], pmul(sim[j], sim[j]));
        u64 npr = pmul(pr, negOne);
        pt  = padd(pt, pr);
        aj0 = padd(aj0, (j & 4) ? npr : pr);   // wire 0 <-> j bit 2
        aj1 = padd(aj1, (j & 2) ? npr : pr);   // wire 1 <-> j bit 1
        aj2 = padd(aj2, (j & 1) ? npr : pr);   // wire 2 <-> j bit 0
    }
    u64 npt = pmul(pt, negOne);
    u64 acc[NW];
    acc[0] = aj0; acc[1] = aj1; acc[2] = aj2;
    acc[3] = (wp & 2) ? npt : pt;              // wire 3 <-> state bit 6
    acc[4] = (wp & 1) ? npt : pt;              // wire 4 <-> state bit 5
#pragma unroll
    for (int w = 5; w < NW; w++)
        acc[w] = ((lane >> (9 - w)) & 1) ? npt : pt;

#pragma unroll
    for (int off = 16; off > 0; off >>= 1) {
#pragma unroll
        for (int w = 0; w < NW; w++)
            acc[w] = padd(acc[w], __shfl_xor_sync(0xFFFFFFFFu, acc[w], off));
    }
    if (lane == 0) {
#pragma unroll
        for (int w = 0; w < NW; w++) wredS[wp][w] = acc[w];
    }
    __syncthreads();
    if (tid < NW) {
        u64 t = padd(padd(wredS[0][tid], wredS[1][tid]),
                     padd(wredS[2][tid], wredS[3][tid]));
        float v0, v1; upk2(t, v0, v1);
        out[b0 * NW + tid]       = v0;
        out[(b0 + 1) * NW + tid] = v1;
    }
}

extern "C" void kernel_launch(void* const* d_in, const int* in_sizes, int n_in,
                              void* d_out, int out_size)
{
    const float* x      = (const float*)d_in[0];   // (2048, 10)
    const float* params = (const float*)d_in[1];   // (4, 6, 10)
    float* out          = (float*)d_out;           // (1, 2048, 10)
    precompute_tables<<<8, 1024>>>(params);
    quantum_pair_kernel<<<1024, 128>>>(x, params, out);
}

// round 13
// speedup vs baseline: 1.4000x; 1.4000x over previous
#include <cuda_runtime.h>

#define NW 10
typedef unsigned long long u64;

// Precomputed tables (params-only, tiny precompute kernel fills them)
__device__ float2 g_tab[8][1024];   // combined diag phases per pass, natural s order
__device__ float2 g_ry[8][NW];      // RY half-angle (cos,sin) per pass/wire
__device__ float2 g_init;           // |0> phase with block-0 rz(p0) folded

// ---------- packed (re,im) f32x2 helpers ----------
__device__ __forceinline__ u64 pk2(float x, float y) {
    u64 r; asm("mov.b64 %0, {%1,%2};" : "=l"(r) : "f"(x), "f"(y)); return r;
}
__device__ __forceinline__ void upk2(u64 v, float &x, float &y) {
    asm("mov.b64 {%0,%1}, %2;" : "=f"(x), "=f"(y) : "l"(v));
}
__device__ __forceinline__ u64 pfma(u64 a, u64 b, u64 c) {
    u64 d; asm("fma.rn.f32x2 %0, %1, %2, %3;" : "=l"(d) : "l"(a), "l"(b), "l"(c)); return d;
}
__device__ __forceinline__ u64 pmul(u64 a, u64 b) {
    u64 d; asm("mul.rn.f32x2 %0, %1, %2;" : "=l"(d) : "l"(a), "l"(b)); return d;
}
__device__ __forceinline__ u64 dup2(float v) { return pk2(v, v); }

__host__ __device__ constexpr int grayC(int x) { return x ^ (x >> 1); }

// ---------- table precompute (identical math to R11, natural order; + RY/init tables) ----------
__global__ void precompute_tables(const float* __restrict__ params) {
    int p = blockIdx.x;          // 0..7
    int s = threadIdx.x;         // 0..1023
    int k = p >> 1, ry = p & 1;

    int idx = s;                 // reference perm chain
    for (int q = 9; q >= 0; --q) {
        int c = q, t = (q + 1) % NW;
        int bit = (idx >> (9 - c)) & 1;
        idx ^= bit << (9 - t);
    }

    const float* thA = params + (k * 6 + (ry ? 5 : 2)) * NW;
    float ang = 0.f;
#pragma unroll
    for (int w = 0; w < NW; w++)
        ang += thA[w] * ((float)((idx >> (9 - w)) & 1) - 0.5f);
    if (ry == 0) {
        const float* th3 = params + (k * 6 + 3) * NW;
#pragma unroll
        for (int w = 0; w < NW; w++)
            ang += th3[w] * ((float)((s >> (9 - w)) & 1) - 0.5f);
    } else if (k < 3) {
        const float* th0 = params + ((k + 1) * 6) * NW;
#pragma unroll
        for (int w = 0; w < NW; w++)
            ang += th0[w] * ((float)((s >> (9 - w)) & 1) - 0.5f);
    }
    float sn, cn; sincosf(ang, &sn, &cn);
    g_tab[p][s] = make_float2(cn, sn);

    if (p == 0) {
        if (s < 80) {
            int pp = s / 10, w = s % 10;
            int kk = pp >> 1, rr = pp & 1;
            float th = 0.5f * params[(kk * 6 + (rr ? 4 : 1)) * NW + w];
            g_ry[pp][w] = make_float2(cosf(th), sinf(th));
        }
        if (s == 80) {
            float a = 0.f;
#pragma unroll
            for (int w = 0; w < NW; w++) a -= 0.5f * params[w];
            float sn2, cn2; sincosf(a, &sn2, &cn2);
            g_init = make_float2(cn2, sn2);
        }
    }
}

// ---------- main kernel: 1 warp per batch element, NO shared memory, NO barriers ----------
// state s = (j<<5) | lane :
//   lane bits 0..4 = state bits 0..4  -> wires 9..5 (shfl butterflies)
//   reg  bits 0..4 = state bits 5..9  -> wires 4..0 (register butterflies)
__global__ __launch_bounds__(32, 20)
void quantum_shfl_kernel(const float* __restrict__ x,
                         float* __restrict__ out)
{
    const int lane = threadIdx.x;
    const int b    = blockIdx.x;
    const unsigned FULL = 0xFFFFFFFFu;

    // encoding precomputes
    float xlane = 0.f;
#pragma unroll
    for (int w = 5; w < NW; w++)
        xlane += x[b * NW + w] * ((float)((lane >> (9 - w)) & 1) - 0.5f);
    float h[5];
#pragma unroll
    for (int w = 0; w < 5; w++) h[w] = 0.5f * x[b * NW + w];
    const float hx0 = 2.f * h[0];   // = x[b][0]

    // perm-shfl per-thread constants
    const int U   = (lane ^ (lane >> 1)) & 31;    // source-lane base
    const int par = __popc(lane) & 1;             // reader-parity bit

    // init |0> with folded phase
    u64 st[32];
#pragma unroll
    for (int j = 0; j < 32; j++) st[j] = 0ull;
    if (lane == 0) {
        float2 gi = g_init;
        st[0] = pk2(gi.x, gi.y);
    }

    // ============================ circuit: 8 half-block passes ============================
#pragma unroll 1
    for (int pass = 0; pass < 8; ++pass) {

        // ---- RY register wires 0..4 (reg bit 4-w) ----
#pragma unroll
        for (int w = 0; w < 5; w++) {
            float2 c = g_ry[pass][w];
            u64 c2 = dup2(c.x), s2 = dup2(c.y), ns2 = dup2(-c.y);
            const int m = 1 << (4 - w);
#pragma unroll
            for (int j = 0; j < 32; j++) {
                if (!(j & m)) {
                    u64 a0 = st[j], a1 = st[j | m];
                    st[j]     = pfma(c2, a0, pmul(ns2, a1));
                    st[j | m] = pfma(s2, a0, pmul(c2, a1));
                }
            }
        }

        // ---- RY lane wires 5..9 (lane bit 9-w, shfl butterflies) ----
#pragma unroll
        for (int w = 5; w < 10; w++) {
            float2 c = g_ry[pass][w];
            u64 c2   = dup2(c.x);
            u64 coef = ((lane >> (9 - w)) & 1) ? dup2(c.y) : dup2(-c.y);
            const int mm = 1 << (9 - w);
#pragma unroll
            for (int j = 0; j < 32; j++) {
                u64 pv = __shfl_xor_sync(FULL, st[j], mm);
                st[j] = pfma(c2, st[j], pmul(coef, pv));
            }
        }

        // ---- perm via shfl.idx, fused with diag (+enc) ----
        const float2* __restrict__ tab = g_tab[pass];
        const bool doEnc = (pass & 1) && (pass < 7);   // passes 1,3,5

#pragma unroll
        for (int jj = 0; jj < 16; jj++) {
            const int gsl     = grayC(jj);              // frees {gsl, gsl^24}
            const int srcLane = U ^ ((jj & 1) << 4);
            const bool sel    = (par ^ (jj & 1)) != 0;

            u64 a  = st[gsl];
            u64 bb = st[gsl ^ 24];
            u64 v0 = __shfl_sync(FULL, sel ? bb : a, srcLane);   // logical jj
            u64 v1 = __shfl_sync(FULL, sel ? a : bb, srcLane);   // logical jj|16

            // diag phases
            float o0x, o0y; upk2(v0, o0x, o0y);
            float2 t0 = tab[(jj << 5) | lane];
            float r0 = o0x * t0.x - o0y * t0.y;
            float i0 = o0x * t0.y + o0y * t0.x;

            float o1x, o1y; upk2(v1, o1x, o1y);
            float2 t1 = tab[((jj | 16) << 5) | lane];
            float r1 = o1x * t1.x - o1y * t1.y;
            float i1 = o1x * t1.y + o1y * t1.x;

            if (doEnc) {
                // wire w (0..4) sign from bit (4-w) of logical j; jj has bit4=0 -> -h[0]
                float ang0 = xlane - h[0]
                    + ((jj & 8) ? h[1] : -h[1]) + ((jj & 4) ? h[2] : -h[2])
                    + ((jj & 2) ? h[3] : -h[3]) + ((jj & 1) ? h[4] : -h[4]);
                float ang1 = ang0 + hx0;
                float se0, ce0, se1, ce1;
                __sincosf(ang0, &se0, &ce0);
                __sincosf(ang1, &se1, &ce1);
                st[gsl]      = pk2(r0 * ce0 - i0 * se0, r0 * se0 + i0 * ce0);
                st[gsl ^ 24] = pk2(r1 * ce1 - i1 * se1, r1 * se1 + i1 * ce1);
            } else {
                st[gsl]      = pk2(r0, i0);
                st[gsl ^ 24] = pk2(r1, i1);
            }
        }

        // ---- renormalize: physical gray(j) holds logical j -> x[p] <- x[gray(p)] ----
        {
            u64 tmp;
            tmp = st[2];  st[2]  = st[3];  st[3]  = tmp;                       // (2 3)
            tmp = st[4];  st[4]  = st[6];  st[6]  = st[5];  st[5]  = st[7];  st[7]  = tmp;   // (4 6 5 7)
            tmp = st[8];  st[8]  = st[12]; st[12] = st[10]; st[10] = st[15]; st[15] = tmp;   // (8 12 10 15)
            tmp = st[9];  st[9]  = st[13]; st[13] = st[11]; st[11] = st[14]; st[14] = tmp;   // (9 13 11 14)
            tmp = st[16]; st[16] = st[24]; st[24] = st[20]; st[20] = st[30]; st[30] = st[17];
            st[17] = st[25]; st[25] = st[21]; st[21] = st[31]; st[31] = tmp;                 // (16 24 20 30 17 25 21 31)
            tmp = st[18]; st[18] = st[27]; st[27] = st[22]; st[22] = st[29]; st[29] = st[19];
            st[19] = st[26]; st[26] = st[23]; st[23] = st[28]; st[28] = tmp;                 // (18 27 22 29 19 26 23 28)
        }
    }

    // ============================ measurement ============================
    float aj[5] = {0.f, 0.f, 0.f, 0.f, 0.f};   // wires 0..4: sign from bit (4-w) of j
    float pt = 0.f;
#pragma unroll
    for (int j = 0; j < 32; j++) {
        float re, im; upk2(st[j], re, im);
        float pr = fmaf(re, re, im * im);
        pt += pr;
        aj[0] += (j & 16) ? -pr : pr;
        aj[1] += (j & 8)  ? -pr : pr;
        aj[2] += (j & 4)  ? -pr : pr;
        aj[3] += (j & 2)  ? -pr : pr;
        aj[4] += (j & 1)  ? -pr : pr;
    }
    float acc[NW];
#pragma unroll
    for (int w = 0; w < 5; w++) acc[w] = aj[w];
#pragma unroll
    for (int w = 5; w < NW; w++)
        acc[w] = ((lane >> (9 - w)) & 1) ? -pt : pt;

#pragma unroll
    for (int off = 16; off > 0; off >>= 1) {
#pragma unroll
        for (int w = 0; w < NW; w++)
            acc[w] += __shfl_xor_sync(FULL, acc[w], off);
    }
    if (lane == 0) {
#pragma unroll
        for (int w = 0; w < NW; w++) out[b * NW + w] = acc[w];
    }
}

extern "C" void kernel_launch(void* const* d_in, const int* in_sizes, int n_in,
                              void* d_out, int out_size)
{
    const float* x      = (const float*)d_in[0];   // (2048, 10)
    const float* params = (const float*)d_in[1];   // (4, 6, 10)
    float* out          = (float*)d_out;           // (1, 2048, 10)
    precompute_tables<<<8, 1024>>>(params);
    quantum_shfl_kernel<<<2048, 32>>>(x, out);
}